// round 13
// baseline (speedup 1.0000x reference)
#include <cuda_runtime.h>
#include <cuda_fp16.h>
#include <cstdint>
#include <math.h>

#define NN 50000
#define EE 1600000
#define GG 256
#define HH 128
#define NGB 391   // ceil(50000/128)

// ---------------- scratch ----------------
__device__ int   g_row[NN + 1];
__device__ int   g_col[EE];
__device__ int   g_fill[NN];
__device__ float g_deginv[NN];
__device__ float g_pool[GG * 2 * HH];
// fp16 hi/lo activation planes
__device__ __align__(16) __half g_xh[NN * HH], g_xl[NN * HH];
__device__ __align__(16) __half g_mh[NN * HH], g_ml[NN * HH];
__device__ __align__(16) __half g_h1h[NN * HH], g_h1l[NN * HH];
__device__ __align__(16) __half g_h2h[NN * HH], g_h2l[NN * HH];
// 12 weight slots of 128x128, fp16 (hi only — 2-term scheme)
__device__ __align__(16) __half g_Wh[12 * 16384];

__device__ __forceinline__ uint32_t smem_u32(const void* p) {
    uint32_t a;
    asm("{ .reg .u64 t; cvta.to.shared.u64 t, %1; cvt.u32.u64 %0, t; }" : "=r"(a) : "l"(p));
    return a;
}
__device__ __forceinline__ uint32_t h2_bits(__half2 h) { return *(uint32_t*)&h; }

// ---------------- prep kernels ----------------
__global__ void k_zero2() {
    int b = blockIdx.x;
    if (b < 196) {
        int i = b * 256 + threadIdx.x;
        if (i < NN) g_fill[i] = 0;
    } else {
        int i = (b - 196) * 256 + threadIdx.x;
        if (i < GG * 256) g_pool[i] = 0.f;
    }
}

__global__ void k_prep(const int* __restrict__ dst, const float* __restrict__ x,
                       const float* s0, const float* s1, const float* s2, const float* s3,
                       const float* s4, const float* s5, const float* s6, const float* s7,
                       const float* s8, const float* s9, const float* s10, const float* s11)
{
    int b = blockIdx.x;
    if (b < 6250) {
        int e = b * 256 + threadIdx.x;
        atomicAdd(&g_fill[dst[e]], 1);
    } else if (b < 12500) {
        int i = ((b - 6250) * 256 + threadIdx.x) * 4;
        float4 v = *(const float4*)(x + i);
        __half2 h01 = __floats2half2_rn(v.x, v.y);
        __half2 h23 = __floats2half2_rn(v.z, v.w);
        *(uint2*)(g_xh + i) = make_uint2(h2_bits(h01), h2_bits(h23));
        float2 r01 = __half22float2(h01);
        float2 r23 = __half22float2(h23);
        __half2 l01 = __floats2half2_rn(v.x - r01.x, v.y - r01.y);
        __half2 l23 = __floats2half2_rn(v.z - r23.x, v.w - r23.y);
        *(uint2*)(g_xl + i) = make_uint2(h2_bits(l01), h2_bits(l23));
    } else {
        int idx = (b - 12500) * 256 + threadIdx.x;   // 12*16384
        int slot = idx >> 14;
        int w = idx & 16383;
        const float* src;
        switch (slot) {
            case 0: src = s0; break; case 1: src = s1; break;
            case 2: src = s2; break; case 3: src = s3; break;
            case 4: src = s4; break; case 5: src = s5; break;
            case 6: src = s6; break; case 7: src = s7; break;
            case 8: src = s8; break; case 9: src = s9; break;
            case 10: src = s10; break; default: src = s11; break;
        }
        g_Wh[idx] = __float2half_rn(src[w]);
    }
}

__global__ void k_scan() {
    __shared__ int ssum[1024];
    int t = threadIdx.x;
    const int C = (NN + 1023) / 1024;
    int s = t * C;
    int e = s + C; if (e > NN) e = NN;
    int loc = 0;
    for (int i = s; i < e; i++) loc += g_fill[i];
    ssum[t] = loc;
    __syncthreads();
    if (t == 0) {
        int run = 0;
        for (int i = 0; i < 1024; i++) { int v = ssum[i]; ssum[i] = run; run += v; }
        g_row[NN] = run;
    }
    __syncthreads();
    int run = ssum[t];
    for (int i = s; i < e; i++) {
        int c = g_fill[i];
        g_row[i]    = run;
        g_fill[i]   = run;
        g_deginv[i] = 1.0f / fmaxf((float)c, 1.0f);
        run += c;
    }
}
__global__ void k_fillcsr(const int* __restrict__ src, const int* __restrict__ dst) {
    int e = blockIdx.x * blockDim.x + threadIdx.x;
    if (e < EE) {
        int pos = atomicAdd(&g_fill[dst[e]], 1);
        g_col[pos] = src[e];
    }
}

// ---------------- standalone aggregation (zero smem, high occupancy) ----------------
__global__ __launch_bounds__(256) void k_agg(const __half* __restrict__ inh) {
    int wid = threadIdx.x >> 5, lane = threadIdx.x & 31;
    int n = blockIdx.x * 8 + wid;
    if (n >= NN) return;
    int s = g_row[n], e = g_row[n + 1];
    float a0 = 0.f, a1 = 0.f, a2 = 0.f, a3 = 0.f;
    const __half* bh = inh + lane * 4;
    #pragma unroll 8
    for (int i = s; i < e; i++) {
        int cc = __ldg(&g_col[i]);
        uint2 uh = *(const uint2*)(bh + (size_t)cc * HH);
        float2 f0 = __half22float2(*(__half2*)&uh.x);
        float2 f1 = __half22float2(*(__half2*)&uh.y);
        a0 += f0.x; a1 += f0.y; a2 += f1.x; a3 += f1.y;
    }
    float d = g_deginv[n];
    a0 *= d; a1 *= d; a2 *= d; a3 *= d;
    __half2 hp0 = __floats2half2_rn(a0, a1);
    __half2 hp1 = __floats2half2_rn(a2, a3);
    *(uint2*)(g_mh + (size_t)n * HH + lane * 4) =
        make_uint2(h2_bits(hp0), h2_bits(hp1));
    float2 r0 = __half22float2(hp0);
    float2 r1 = __half22float2(hp1);
    __half2 lp0 = __floats2half2_rn(a0 - r0.x, a1 - r0.y);
    __half2 lp1 = __floats2half2_rn(a2 - r1.x, a3 - r1.y);
    *(uint2*)(g_ml + (size_t)n * HH + lane * 4) =
        make_uint2(h2_bits(lp0), h2_bits(lp1));
}

// ---------------- GEMM (M128 x N64 tiles, 3 CTAs/SM) ----------------
// SMEM: Ah 32KB | Al 32KB | W 8KB (64 k-rows x 64 cols, 128B-row swizzle) | bias
static constexpr int OFF_AH = 0;
static constexpr int OFF_AL = 32768;
static constexpr int OFF_W  = 65536;
static constexpr int OFF_BI = 73728;
static constexpr int GEMM_SMEM = 74240;

// 256B-row swizzle (A planes)
__device__ __forceinline__ uint32_t swz(uint32_t row, uint32_t kbyte) {
    uint32_t col16 = kbyte >> 4;
    uint32_t scol = col16 ^ (row & 7);
    return row * 256 + scol * 16 + (kbyte & 15);
}
// 128B-row swizzle (W tile)
__device__ __forceinline__ uint32_t swzW(uint32_t row, uint32_t kbyte) {
    uint32_t col16 = kbyte >> 4;             // 0..7
    uint32_t scol = col16 ^ (row & 7);
    return row * 128 + scol * 16 + (kbyte & 15);
}
__device__ __forceinline__ void ldsm_x4(uint32_t* r, uint32_t addr) {
    asm volatile("ldmatrix.sync.aligned.m8n8.x4.shared.b16 {%0,%1,%2,%3}, [%4];"
                 : "=r"(r[0]), "=r"(r[1]), "=r"(r[2]), "=r"(r[3]) : "r"(addr));
}
__device__ __forceinline__ void ldsm_x4_t(uint32_t* r, uint32_t addr) {
    asm volatile("ldmatrix.sync.aligned.m8n8.x4.trans.shared.b16 {%0,%1,%2,%3}, [%4];"
                 : "=r"(r[0]), "=r"(r[1]), "=r"(r[2]), "=r"(r[3]) : "r"(addr));
}
__device__ __forceinline__ void mma16816(float* c, const uint32_t* a, uint32_t b0, uint32_t b1) {
    asm volatile(
        "mma.sync.aligned.m16n8k16.row.col.f32.f16.f16.f32 "
        "{%0,%1,%2,%3}, {%4,%5,%6,%7}, {%8,%9}, {%0,%1,%2,%3};"
        : "+f"(c[0]), "+f"(c[1]), "+f"(c[2]), "+f"(c[3])
        : "r"(a[0]), "r"(a[1]), "r"(a[2]), "r"(a[3]), "r"(b0), "r"(b1));
}

// one panel, 2-term, N=64 half: (Ah+Al)[128x128] @ Wh[:, ncol0:ncol0+64]
__device__ __forceinline__ void panel_mma64(
    float acc[2][4][4], int slot, int ncol0, char* smem, uint32_t sb,
    int tid, int lane, int wm, int wn)
{
    const __half* wh = g_Wh + slot * 16384;
    uint32_t aRow = (uint32_t)(wm + (lane & 15));
    uint32_t aKadd = (uint32_t)((lane >> 4) * 16);
    uint32_t wRowL = (uint32_t)(lane & 15);
    uint32_t nAdd = (uint32_t)((lane >> 4) * 16);
    int k = tid >> 2, q4 = tid & 3;

    #pragma unroll
    for (int c = 0; c < 2; c++) {
        __syncthreads();   // A visible / prev W consumed
        {
            // stage W chunk: 64 k-rows x 64 cols (global cols ncol0..+64)
            const uint4* wp = (const uint4*)(wh + (size_t)(c * 64 + k) * 128 + ncol0 + q4 * 16);
            uint4 w0 = wp[0], w1 = wp[1];
            *(uint4*)(smem + OFF_W + swzW((uint32_t)k, (uint32_t)(q4 * 32))) = w0;
            *(uint4*)(smem + OFF_W + swzW((uint32_t)k, (uint32_t)(q4 * 32 + 16))) = w1;
        }
        __syncthreads();
        #pragma unroll
        for (int ks = 0; ks < 4; ks++) {
            uint32_t kb = (uint32_t)(c * 128 + ks * 32) + aKadd;
            uint32_t ah0[4], ah1[4], al0[4], al1[4];
            ldsm_x4(ah0, sb + OFF_AH + swz(aRow, kb));
            ldsm_x4(ah1, sb + OFF_AH + swz(aRow + 16, kb));
            ldsm_x4(al0, sb + OFF_AL + swz(aRow, kb));
            ldsm_x4(al1, sb + OFF_AL + swz(aRow + 16, kb));
            uint32_t wRow = (uint32_t)(ks * 16) + wRowL;
            #pragma unroll
            for (int bt = 0; bt < 2; bt++) {
                uint32_t nb = (uint32_t)((wn + bt * 16) * 2) + nAdd;
                uint32_t bh[4];
                ldsm_x4_t(bh, sb + OFF_W + swzW(wRow, nb));
                mma16816(acc[0][bt * 2 + 0], ah0, bh[0], bh[1]);
                mma16816(acc[0][bt * 2 + 1], ah0, bh[2], bh[3]);
                mma16816(acc[1][bt * 2 + 0], ah1, bh[0], bh[1]);
                mma16816(acc[1][bt * 2 + 1], ah1, bh[2], bh[3]);
                mma16816(acc[0][bt * 2 + 0], al0, bh[0], bh[1]);
                mma16816(acc[0][bt * 2 + 1], al0, bh[2], bh[3]);
                mma16816(acc[1][bt * 2 + 0], al1, bh[0], bh[1]);
                mma16816(acc[1][bt * 2 + 1], al1, bh[2], bh[3]);
            }
        }
    }
}

// stage direct plane rows into SMEM A (full K=128)
__device__ __forceinline__ void stage_direct(
    const __half* Ah, const __half* Al,
    int m0, int tid, char* smem)
{
    int r = tid >> 1, half_ = tid & 1;
    int gr = m0 + r; if (gr > NN - 1) gr = NN - 1;
    size_t gofs = (size_t)gr * 128 + half_ * 64;
    const uint4* aph = (const uint4*)(Ah + gofs);
    const uint4* apl = (const uint4*)(Al + gofs);
    #pragma unroll
    for (int q = 0; q < 8; q++) {
        uint32_t kb = (uint32_t)(half_ * 128 + q * 16);
        uint32_t so = swz((uint32_t)r, kb);
        *(uint4*)(smem + OFF_AH + so) = aph[q];
        *(uint4*)(smem + OFF_AL + so) = apl[q];
    }
}

// epilogue N=64: bias+relu; plane store and/or pool
__device__ __forceinline__ void epilogue64(
    float acc[2][4][4], const float* sB, int ncol0,
    __half* outh, __half* outl,
    const int* batch, int poolOff,
    int m0, int lane, int wm, int wn)
{
    int g = lane >> 2, tg = lane & 3;
    #pragma unroll
    for (int mt = 0; mt < 2; mt++) {
        #pragma unroll
        for (int half_ = 0; half_ < 2; half_++) {
            int r = m0 + wm + mt * 16 + g + half_ * 8;
            if (r >= NN) continue;
            int bi = batch ? batch[r] : 0;
            #pragma unroll
            for (int nt = 0; nt < 4; nt++) {
                int col = ncol0 + wn + nt * 8 + tg * 2;
                float vx = fmaxf(acc[mt][nt][half_ * 2 + 0] + sB[col], 0.f);
                float vy = fmaxf(acc[mt][nt][half_ * 2 + 1] + sB[col + 1], 0.f);
                if (outh) {
                    __half2 hp = __floats2half2_rn(vx, vy);
                    *(uint32_t*)(outh + (size_t)r * 128 + col) = h2_bits(hp);
                    float2 hr = __half22float2(hp);
                    __half2 lp = __floats2half2_rn(vx - hr.x, vy - hr.y);
                    *(uint32_t*)(outl + (size_t)r * 128 + col) = h2_bits(lp);
                }
                if (batch) {
                    float* pp = g_pool + (size_t)bi * 256 + poolOff + col;
                    atomicAdd(pp + 0, vx);
                    atomicAdd(pp + 1, vy);
                }
            }
        }
    }
}

// conv GEMM (N-split): relu(mean@slotL + in@slotR + bias) -> planes
__global__ __launch_bounds__(256, 3) void k_conv(
    const __half* __restrict__ inh, const __half* __restrict__ inl,
    int slotL, int slotR, const float* __restrict__ bias,
    __half* __restrict__ outh, __half* __restrict__ outl)
{
    extern __shared__ char smem[];
    uint32_t sb = smem_u32(smem);
    int tid = threadIdx.x, lane = tid & 31, wid = tid >> 5;
    int wm = (wid & 3) * 32, wn = (wid >> 2) * 32;
    int t = blockIdx.x >> 1;
    int ncol0 = (blockIdx.x & 1) * 64;
    int m0 = t * 128;
    float* sB = (float*)(smem + OFF_BI);
    if (tid < 128) sB[tid] = bias[tid];

    float acc[2][4][4];
    #pragma unroll
    for (int a = 0; a < 2; a++)
        #pragma unroll
        for (int b = 0; b < 4; b++)
            #pragma unroll
            for (int c = 0; c < 4; c++) acc[a][b][c] = 0.f;

    stage_direct(g_mh, g_ml, m0, tid, smem);
    panel_mma64(acc, slotL, ncol0, smem, sb, tid, lane, wm, wn);
    __syncthreads();
    stage_direct(inh, inl, m0, tid, smem);
    panel_mma64(acc, slotR, ncol0, smem, sb, tid, lane, wm, wn);

    epilogue64(acc, sB, ncol0, outh, outl, nullptr, 0, m0, lane, wm, wn);
}

// JK (N-split): relu(A1@s1 + A2@s2 + bias), plane store + pool
__global__ __launch_bounds__(256, 3) void k_gemmJK(
    const __half* __restrict__ A1h, const __half* __restrict__ A1l, int s1,
    const __half* __restrict__ A2h, const __half* __restrict__ A2l, int s2,
    const float* __restrict__ bias,
    __half* __restrict__ outh, __half* __restrict__ outl,
    const int* __restrict__ batch, int poolOff)
{
    extern __shared__ char smem[];
    uint32_t sb = smem_u32(smem);
    int tid = threadIdx.x, lane = tid & 31, wid = tid >> 5;
    int wm = (wid & 3) * 32, wn = (wid >> 2) * 32;
    int t = blockIdx.x >> 1;
    int ncol0 = (blockIdx.x & 1) * 64;
    int m0 = t * 128;
    float* sB = (float*)(smem + OFF_BI);
    if (tid < 128) sB[tid] = bias[tid];

    float acc[2][4][4];
    #pragma unroll
    for (int a = 0; a < 2; a++)
        #pragma unroll
        for (int b = 0; b < 4; b++)
            #pragma unroll
            for (int c = 0; c < 4; c++) acc[a][b][c] = 0.f;

    stage_direct(A1h, A1l, m0, tid, smem);
    panel_mma64(acc, s1, ncol0, smem, sb, tid, lane, wm, wn);
    __syncthreads();
    stage_direct(A2h, A2l, m0, tid, smem);
    panel_mma64(acc, s2, ncol0, smem, sb, tid, lane, wm, wn);

    epilogue64(acc, sB, ncol0, outh, outl, batch, poolOff, m0, lane, wm, wn);
}

// ---------------- head ----------------
__global__ void k_head(const float* __restrict__ gamma, const float* __restrict__ beta,
                       const float* __restrict__ rm, const float* __restrict__ rv,
                       const float* __restrict__ W1, const float* __restrict__ b1,
                       const float* __restrict__ W2, const float* __restrict__ b2,
                       float* __restrict__ out)
{
    __shared__ float sg[256];
    __shared__ float s1[128];
    __shared__ float s2[10];
    int gb = blockIdx.x, t = threadIdx.x;
    for (int i = t; i < 256; i += 128) {
        float v = g_pool[gb * 256 + i];
        v = (v - rm[i]) * rsqrtf(rv[i] + 1e-5f) * gamma[i] + beta[i];
        sg[i] = v;
    }
    __syncthreads();
    float acc = b1[t];
    #pragma unroll 8
    for (int k = 0; k < 256; k++) acc += sg[k] * W1[k * 128 + t];
    s1[t] = fmaxf(acc, 0.f);
    __syncthreads();
    if (t < 10) {
        float a = b2[t];
        #pragma unroll 8
        for (int k = 0; k < 128; k++) a += s1[k] * W2[k * 10 + t];
        s2[t] = a;
    }
    __syncthreads();
    if (t == 0) {
        float m = s2[0];
        for (int j = 1; j < 10; j++) m = fmaxf(m, s2[j]);
        float ex[10]; float sum = 0.f;
        for (int j = 0; j < 10; j++) { ex[j] = expf(s2[j] - m); sum += ex[j]; }
        float inv = 1.0f / sum;
        for (int j = 0; j < 10; j++) out[gb * 10 + j] = ex[j] * inv;
    }
}

// ---------------- host launch ----------------
extern "C" void kernel_launch(void* const* d_in, const int* in_sizes, int n_in,
                              void* d_out, int out_size)
{
    const float* x     = (const float*)d_in[0];
    const int*   ei    = (const int*)d_in[1];
    const int*   batch = (const int*)d_in[2];
    int base = (n_in > 3 && in_sizes[3] == 1) ? 4 : 3;

    const float* p[24];
    for (int i = 0; i < 24; i++) p[i] = (const float*)d_in[base + i];

    const int* src = ei;
    const int* dst = ei + EE;

    void *pxh, *pxl, *ph1h, *ph1l, *ph2h, *ph2l;
    cudaGetSymbolAddress(&pxh,  g_xh);
    cudaGetSymbolAddress(&pxl,  g_xl);
    cudaGetSymbolAddress(&ph1h, g_h1h);
    cudaGetSymbolAddress(&ph1l, g_h1l);
    cudaGetSymbolAddress(&ph2h, g_h2h);
    cudaGetSymbolAddress(&ph2l, g_h2l);

    __half* xh  = (__half*)pxh;
    __half* xl  = (__half*)pxl;
    __half* h1h = (__half*)ph1h;
    __half* h1l = (__half*)ph1l;
    __half* h2h = (__half*)ph2h;
    __half* h2l = (__half*)ph2l;

    // x planes freed after block-0 conv1 -> reuse as block-0 output (hb)
    __half* hbh = xh;
    __half* hbl = xl;

    cudaFuncSetAttribute(k_conv,   cudaFuncAttributeMaxDynamicSharedMemorySize, GEMM_SMEM);
    cudaFuncSetAttribute(k_gemmJK, cudaFuncAttributeMaxDynamicSharedMemorySize, GEMM_SMEM);

    // ---- prep (g_fill/g_pool zeroed by previous call's tail; zero-init at load) ----
    k_prep<<<13268, 256>>>(dst, x,
        p[0], p[1], p[3], p[4], p[6], p[6] + 16384,
        p[8], p[9], p[11], p[12], p[14], p[14] + 16384);
    k_scan<<<1, 1024>>>();
    k_fillcsr<<<(EE + 255) / 256, 256>>>(src, dst);

    const int AGG_BLOCKS = (NN + 7) / 8;   // 6250
    const int GEMM_GRID = NGB * 2;         // 782

    // ---- block 0, conv1 ----
    k_agg<<<AGG_BLOCKS, 256>>>(xh);
    k_conv<<<GEMM_GRID, 256, GEMM_SMEM>>>(xh, xl, 0, 1, p[2], h1h, h1l);
    // ---- block 0, conv2 ----
    k_agg<<<AGG_BLOCKS, 256>>>(h1h);
    k_conv<<<GEMM_GRID, 256, GEMM_SMEM>>>(h1h, h1l, 2, 3, p[5], h2h, h2l);
    // ---- block 0 JK + pool 0 ----
    k_gemmJK<<<GEMM_GRID, 256, GEMM_SMEM>>>(h1h, h1l, 4, h2h, h2l, 5, p[7], hbh, hbl, batch, 0);

    // ---- block 1, conv1 ----
    k_agg<<<AGG_BLOCKS, 256>>>(hbh);
    k_conv<<<GEMM_GRID, 256, GEMM_SMEM>>>(hbh, hbl, 6, 7, p[10], h1h, h1l);
    // ---- block 1, conv2 ----
    k_agg<<<AGG_BLOCKS, 256>>>(h1h);
    k_conv<<<GEMM_GRID, 256, GEMM_SMEM>>>(h1h, h1l, 8, 9, p[13], h2h, h2l);
    // ---- block 1 JK + pool 1 (pool only) ----
    k_gemmJK<<<GEMM_GRID, 256, GEMM_SMEM>>>(h1h, h1l, 10, h2h, h2l, 11, p[15],
                                            nullptr, nullptr, batch, 128);

    // ---- head ----
    k_head<<<GG, 128>>>(p[16], p[17], p[18], p[19], p[20], p[21], p[22], p[23],
                        (float*)d_out);

    // ---- tail: restore zeroed state for the next call ----
    k_zero2<<<452, 256>>>();
}

// round 14
// speedup vs baseline: 1.1448x; 1.1448x over previous
#include <cuda_runtime.h>
#include <cuda_fp16.h>
#include <cstdint>
#include <math.h>

#define NN 50000
#define EE 1600000
#define GG 256
#define HH 128
#define NGB 391   // ceil(50000/128)

// ---------------- scratch ----------------
__device__ int   g_row[NN + 1];
__device__ int   g_col[EE];
__device__ int   g_fill[NN];
__device__ float g_deginv[NN];
__device__ float g_pool[GG * 2 * HH];
// fp16 hi/lo activation planes
__device__ __align__(16) __half g_xh[NN * HH], g_xl[NN * HH];
__device__ __align__(16) __half g_mh[NN * HH], g_ml[NN * HH];
__device__ __align__(16) __half g_ph[NN * HH], g_pl[NN * HH];   // preact planes
__device__ __align__(16) __half g_h1h[NN * HH], g_h1l[NN * HH];
__device__ __align__(16) __half g_h2h[NN * HH], g_h2l[NN * HH];
// 12 weight slots of 128x128, fp16 (hi only — 2-term scheme)
__device__ __align__(16) __half g_Wh[12 * 16384];

__device__ __forceinline__ uint32_t smem_u32(const void* p) {
    uint32_t a;
    asm("{ .reg .u64 t; cvta.to.shared.u64 t, %1; cvt.u32.u64 %0, t; }" : "=r"(a) : "l"(p));
    return a;
}
__device__ __forceinline__ uint32_t h2_bits(__half2 h) { return *(uint32_t*)&h; }

// ---------------- prep kernels ----------------
__global__ void k_zero2() {
    int b = blockIdx.x;
    if (b < 196) {
        int i = b * 256 + threadIdx.x;
        if (i < NN) g_fill[i] = 0;
    } else {
        int i = (b - 196) * 256 + threadIdx.x;
        if (i < GG * 256) g_pool[i] = 0.f;
    }
}

__global__ void k_count(const int* __restrict__ dst) {
    int e = blockIdx.x * 256 + threadIdx.x;
    if (e < EE) atomicAdd(&g_fill[dst[e]], 1);
}

// x->fp16 hi/lo planes | W->fp16 (runs on side stream, overlapped with CSR build)
__global__ void k_convxw(const float* __restrict__ x,
                         const float* s0, const float* s1, const float* s2, const float* s3,
                         const float* s4, const float* s5, const float* s6, const float* s7,
                         const float* s8, const float* s9, const float* s10, const float* s11)
{
    int b = blockIdx.x;
    if (b < 6250) {
        int i = (b * 256 + threadIdx.x) * 4;
        float4 v = *(const float4*)(x + i);
        __half2 h01 = __floats2half2_rn(v.x, v.y);
        __half2 h23 = __floats2half2_rn(v.z, v.w);
        *(uint2*)(g_xh + i) = make_uint2(h2_bits(h01), h2_bits(h23));
        float2 r01 = __half22float2(h01);
        float2 r23 = __half22float2(h23);
        __half2 l01 = __floats2half2_rn(v.x - r01.x, v.y - r01.y);
        __half2 l23 = __floats2half2_rn(v.z - r23.x, v.w - r23.y);
        *(uint2*)(g_xl + i) = make_uint2(h2_bits(l01), h2_bits(l23));
    } else {
        int idx = (b - 6250) * 256 + threadIdx.x;   // 12*16384
        int slot = idx >> 14;
        int w = idx & 16383;
        const float* src;
        switch (slot) {
            case 0: src = s0; break; case 1: src = s1; break;
            case 2: src = s2; break; case 3: src = s3; break;
            case 4: src = s4; break; case 5: src = s5; break;
            case 6: src = s6; break; case 7: src = s7; break;
            case 8: src = s8; break; case 9: src = s9; break;
            case 10: src = s10; break; default: src = s11; break;
        }
        g_Wh[idx] = __float2half_rn(src[w]);
    }
}

__global__ void k_scan() {
    __shared__ int ssum[1024];
    int t = threadIdx.x;
    const int C = (NN + 1023) / 1024;
    int s = t * C;
    int e = s + C; if (e > NN) e = NN;
    int loc = 0;
    for (int i = s; i < e; i++) loc += g_fill[i];
    ssum[t] = loc;
    __syncthreads();
    if (t == 0) {
        int run = 0;
        for (int i = 0; i < 1024; i++) { int v = ssum[i]; ssum[i] = run; run += v; }
        g_row[NN] = run;
    }
    __syncthreads();
    int run = ssum[t];
    for (int i = s; i < e; i++) {
        int c = g_fill[i];
        g_row[i]    = run;
        g_fill[i]   = run;
        g_deginv[i] = 1.0f / fmaxf((float)c, 1.0f);
        run += c;
    }
}
__global__ void k_fillcsr(const int* __restrict__ src, const int* __restrict__ dst) {
    int e = blockIdx.x * blockDim.x + threadIdx.x;
    if (e < EE) {
        int pos = atomicAdd(&g_fill[dst[e]], 1);
        g_col[pos] = src[e];
    }
}

// ---------------- aggregation: 2 nodes/warp, 16 lanes x uint4 ----------------
__global__ __launch_bounds__(256) void k_agg(const __half* __restrict__ inh) {
    int tid = threadIdx.x;
    int warp = tid >> 5, lane = tid & 31;
    int l16 = lane & 15;
    int n = blockIdx.x * 16 + warp * 2 + (lane >> 4);
    if (n >= NN) return;
    int s = g_row[n], e = g_row[n + 1];
    float a0 = 0.f, a1 = 0.f, a2 = 0.f, a3 = 0.f;
    float a4 = 0.f, a5 = 0.f, a6 = 0.f, a7 = 0.f;
    const __half* bh = inh + l16 * 8;
    #pragma unroll 4
    for (int i = s; i < e; i++) {
        int cc = __ldg(&g_col[i]);
        uint4 u = *(const uint4*)(bh + (size_t)cc * HH);
        float2 f0 = __half22float2(*(__half2*)&u.x);
        float2 f1 = __half22float2(*(__half2*)&u.y);
        float2 f2 = __half22float2(*(__half2*)&u.z);
        float2 f3 = __half22float2(*(__half2*)&u.w);
        a0 += f0.x; a1 += f0.y; a2 += f1.x; a3 += f1.y;
        a4 += f2.x; a5 += f2.y; a6 += f3.x; a7 += f3.y;
    }
    float d = g_deginv[n];
    a0 *= d; a1 *= d; a2 *= d; a3 *= d;
    a4 *= d; a5 *= d; a6 *= d; a7 *= d;
    __half2 hp0 = __floats2half2_rn(a0, a1);
    __half2 hp1 = __floats2half2_rn(a2, a3);
    __half2 hp2 = __floats2half2_rn(a4, a5);
    __half2 hp3 = __floats2half2_rn(a6, a7);
    *(uint4*)(g_mh + (size_t)n * HH + l16 * 8) =
        make_uint4(h2_bits(hp0), h2_bits(hp1), h2_bits(hp2), h2_bits(hp3));
    float2 r0 = __half22float2(hp0), r1 = __half22float2(hp1);
    float2 r2 = __half22float2(hp2), r3 = __half22float2(hp3);
    __half2 lp0 = __floats2half2_rn(a0 - r0.x, a1 - r0.y);
    __half2 lp1 = __floats2half2_rn(a2 - r1.x, a3 - r1.y);
    __half2 lp2 = __floats2half2_rn(a4 - r2.x, a5 - r2.y);
    __half2 lp3 = __floats2half2_rn(a6 - r3.x, a7 - r3.y);
    *(uint4*)(g_ml + (size_t)n * HH + l16 * 8) =
        make_uint4(h2_bits(lp0), h2_bits(lp1), h2_bits(lp2), h2_bits(lp3));
}

// ---------------- GEMM (R12 shape: 128x128 tile, 2 CTA/SM) ----------------
static constexpr int OFF_AH = 0;
static constexpr int OFF_AL = 32768;
static constexpr int OFF_WH = 65536;
static constexpr int OFF_BI = 81920;
static constexpr int GEMM_SMEM = 82432;

__device__ __forceinline__ uint32_t swz(uint32_t row, uint32_t kbyte) {
    uint32_t col16 = kbyte >> 4;
    uint32_t scol = col16 ^ (row & 7);
    return row * 256 + scol * 16 + (kbyte & 15);
}
__device__ __forceinline__ void ldsm_x4(uint32_t* r, uint32_t addr) {
    asm volatile("ldmatrix.sync.aligned.m8n8.x4.shared.b16 {%0,%1,%2,%3}, [%4];"
                 : "=r"(r[0]), "=r"(r[1]), "=r"(r[2]), "=r"(r[3]) : "r"(addr));
}
__device__ __forceinline__ void ldsm_x4_t(uint32_t* r, uint32_t addr) {
    asm volatile("ldmatrix.sync.aligned.m8n8.x4.trans.shared.b16 {%0,%1,%2,%3}, [%4];"
                 : "=r"(r[0]), "=r"(r[1]), "=r"(r[2]), "=r"(r[3]) : "r"(addr));
}
__device__ __forceinline__ void mma16816(float* c, const uint32_t* a, uint32_t b0, uint32_t b1) {
    asm volatile(
        "mma.sync.aligned.m16n8k16.row.col.f32.f16.f16.f32 "
        "{%0,%1,%2,%3}, {%4,%5,%6,%7}, {%8,%9}, {%0,%1,%2,%3};"
        : "+f"(c[0]), "+f"(c[1]), "+f"(c[2]), "+f"(c[3])
        : "r"(a[0]), "r"(a[1]), "r"(a[2]), "r"(a[3]), "r"(b0), "r"(b1));
}

__device__ __forceinline__ void panel_mma(
    float acc[2][8][4], int slot, char* smem, uint32_t sb,
    int tid, int lane, int wm, int wn)
{
    const __half* wh = g_Wh + slot * 16384;
    uint32_t aRow = (uint32_t)(wm + (lane & 15));
    uint32_t aKadd = (uint32_t)((lane >> 4) * 16);
    uint32_t wRowL = (uint32_t)(lane & 15);
    uint32_t nAdd = (uint32_t)((lane >> 4) * 16);
    int k = tid >> 2, q4 = tid & 3;

    #pragma unroll
    for (int c = 0; c < 2; c++) {
        __syncthreads();
        {
            const uint4* whp = (const uint4*)(wh + (size_t)(c * 64 + k) * 128 + q4 * 32);
            #pragma unroll
            for (int q = 0; q < 4; q++) {
                uint32_t b = (uint32_t)(q4 * 64 + q * 16);
                *(uint4*)(smem + OFF_WH + swz((uint32_t)k, b)) = whp[q];
            }
        }
        __syncthreads();
        #pragma unroll
        for (int ks = 0; ks < 4; ks++) {
            uint32_t kb = (uint32_t)(c * 128 + ks * 32) + aKadd;
            uint32_t ah0[4], ah1[4], al0[4], al1[4];
            ldsm_x4(ah0, sb + OFF_AH + swz(aRow, kb));
            ldsm_x4(ah1, sb + OFF_AH + swz(aRow + 16, kb));
            ldsm_x4(al0, sb + OFF_AL + swz(aRow, kb));
            ldsm_x4(al1, sb + OFF_AL + swz(aRow + 16, kb));
            uint32_t wRow = (uint32_t)(ks * 16) + wRowL;
            #pragma unroll
            for (int bt = 0; bt < 4; bt++) {
                uint32_t nb = (uint32_t)((wn + bt * 16) * 2) + nAdd;
                uint32_t bh[4];
                ldsm_x4_t(bh, sb + OFF_WH + swz(wRow, nb));
                mma16816(acc[0][bt * 2 + 0], ah0, bh[0], bh[1]);
                mma16816(acc[0][bt * 2 + 1], ah0, bh[2], bh[3]);
                mma16816(acc[1][bt * 2 + 0], ah1, bh[0], bh[1]);
                mma16816(acc[1][bt * 2 + 1], ah1, bh[2], bh[3]);
                mma16816(acc[0][bt * 2 + 0], al0, bh[0], bh[1]);
                mma16816(acc[0][bt * 2 + 1], al0, bh[2], bh[3]);
                mma16816(acc[1][bt * 2 + 0], al1, bh[0], bh[1]);
                mma16816(acc[1][bt * 2 + 1], al1, bh[2], bh[3]);
            }
        }
    }
}

__device__ __forceinline__ void stage_direct(
    const __half* Ah, const __half* Al,
    int m0, int tid, char* smem)
{
    int r = tid >> 1, half_ = tid & 1;
    int gr = m0 + r; if (gr > NN - 1) gr = NN - 1;
    size_t gofs = (size_t)gr * 128 + half_ * 64;
    const uint4* aph = (const uint4*)(Ah + gofs);
    const uint4* apl = (const uint4*)(Al + gofs);
    #pragma unroll
    for (int q = 0; q < 8; q++) {
        uint32_t kb = (uint32_t)(half_ * 128 + q * 16);
        uint32_t so = swz((uint32_t)r, kb);
        *(uint4*)(smem + OFF_AH + so) = aph[q];
        *(uint4*)(smem + OFF_AL + so) = apl[q];
    }
}

// ---------------- P2: preact = in @ Wr -> fp16 hi/lo preact planes ----------------
__global__ __launch_bounds__(256, 2) void k_p2(
    const __half* __restrict__ inh, const __half* __restrict__ inl, int slotR)
{
    extern __shared__ char smem[];
    uint32_t sb = smem_u32(smem);
    int tid = threadIdx.x, lane = tid & 31, wid = tid >> 5;
    int wm = (wid & 3) * 32, wn = (wid >> 2) * 64;
    int m0 = blockIdx.x * 128;

    float acc[2][8][4];
    #pragma unroll
    for (int a = 0; a < 2; a++)
        #pragma unroll
        for (int b = 0; b < 8; b++)
            #pragma unroll
            for (int c = 0; c < 4; c++) acc[a][b][c] = 0.f;

    stage_direct(inh, inl, m0, tid, smem);
    panel_mma(acc, slotR, smem, sb, tid, lane, wm, wn);

    int g = lane >> 2, tg = lane & 3;
    #pragma unroll
    for (int mt = 0; mt < 2; mt++) {
        #pragma unroll
        for (int half_ = 0; half_ < 2; half_++) {
            int r = m0 + wm + mt * 16 + g + half_ * 8;
            if (r >= NN) continue;
            #pragma unroll
            for (int nt = 0; nt < 8; nt++) {
                int col = wn + nt * 8 + tg * 2;
                float vx = acc[mt][nt][half_ * 2 + 0];
                float vy = acc[mt][nt][half_ * 2 + 1];
                __half2 hp = __floats2half2_rn(vx, vy);
                *(uint32_t*)(g_ph + (size_t)r * 128 + col) = h2_bits(hp);
                float2 hr = __half22float2(hp);
                __half2 lp = __floats2half2_rn(vx - hr.x, vy - hr.y);
                *(uint32_t*)(g_pl + (size_t)r * 128 + col) = h2_bits(lp);
            }
        }
    }
}

// ---------------- P1: out = relu(mean@Wl + preact + bias) -> planes ----------------
__global__ __launch_bounds__(256, 2) void k_p1(
    int slotL, const float* __restrict__ bias,
    __half* __restrict__ outh, __half* __restrict__ outl)
{
    extern __shared__ char smem[];
    uint32_t sb = smem_u32(smem);
    int tid = threadIdx.x, lane = tid & 31, wid = tid >> 5;
    int wm = (wid & 3) * 32, wn = (wid >> 2) * 64;
    int m0 = blockIdx.x * 128;
    float* sB = (float*)(smem + OFF_BI);
    if (tid < 128) sB[tid] = bias[tid];

    float acc[2][8][4];
    #pragma unroll
    for (int a = 0; a < 2; a++)
        #pragma unroll
        for (int b = 0; b < 8; b++)
            #pragma unroll
            for (int c = 0; c < 4; c++) acc[a][b][c] = 0.f;

    stage_direct(g_mh, g_ml, m0, tid, smem);
    panel_mma(acc, slotL, smem, sb, tid, lane, wm, wn);

    int g = lane >> 2, tg = lane & 3;
    #pragma unroll
    for (int mt = 0; mt < 2; mt++) {
        #pragma unroll
        for (int half_ = 0; half_ < 2; half_++) {
            int r = m0 + wm + mt * 16 + g + half_ * 8;
            if (r >= NN) continue;
            #pragma unroll
            for (int nt = 0; nt < 8; nt++) {
                int col = wn + nt * 8 + tg * 2;
                uint32_t ph = *(uint32_t*)(g_ph + (size_t)r * 128 + col);
                uint32_t pl = *(uint32_t*)(g_pl + (size_t)r * 128 + col);
                float2 fh = __half22float2(*(__half2*)&ph);
                float2 fl = __half22float2(*(__half2*)&pl);
                float vx = fmaxf(acc[mt][nt][half_ * 2 + 0] + fh.x + fl.x + sB[col], 0.f);
                float vy = fmaxf(acc[mt][nt][half_ * 2 + 1] + fh.y + fl.y + sB[col + 1], 0.f);
                __half2 hp = __floats2half2_rn(vx, vy);
                *(uint32_t*)(outh + (size_t)r * 128 + col) = h2_bits(hp);
                float2 hr = __half22float2(hp);
                __half2 lp = __floats2half2_rn(vx - hr.x, vy - hr.y);
                *(uint32_t*)(outl + (size_t)r * 128 + col) = h2_bits(lp);
            }
        }
    }
}

// ---------------- JK: relu(A1@s1 + A2@s2 + bias), plane store + pool ----------------
__global__ __launch_bounds__(256, 2) void k_gemmJK(
    const __half* __restrict__ A1h, const __half* __restrict__ A1l, int s1,
    const __half* __restrict__ A2h, const __half* __restrict__ A2l, int s2,
    const float* __restrict__ bias,
    __half* __restrict__ outh, __half* __restrict__ outl,
    const int* __restrict__ batch, int poolOff)
{
    extern __shared__ char smem[];
    uint32_t sb = smem_u32(smem);
    int tid = threadIdx.x, lane = tid & 31, wid = tid >> 5;
    int wm = (wid & 3) * 32, wn = (wid >> 2) * 64;
    int m0 = blockIdx.x * 128;
    float* sB = (float*)(smem + OFF_BI);
    if (tid < 128) sB[tid] = bias[tid];

    float acc[2][8][4];
    #pragma unroll
    for (int a = 0; a < 2; a++)
        #pragma unroll
        for (int b = 0; b < 8; b++)
            #pragma unroll
            for (int c = 0; c < 4; c++) acc[a][b][c] = 0.f;

    stage_direct(A1h, A1l, m0, tid, smem);
    panel_mma(acc, s1, smem, sb, tid, lane, wm, wn);
    __syncthreads();
    stage_direct(A2h, A2l, m0, tid, smem);
    panel_mma(acc, s2, smem, sb, tid, lane, wm, wn);

    int g = lane >> 2, tg = lane & 3;
    #pragma unroll
    for (int mt = 0; mt < 2; mt++) {
        #pragma unroll
        for (int half_ = 0; half_ < 2; half_++) {
            int r = m0 + wm + mt * 16 + g + half_ * 8;
            if (r >= NN) continue;
            int bi = batch ? batch[r] : 0;
            #pragma unroll
            for (int nt = 0; nt < 8; nt++) {
                int col = wn + nt * 8 + tg * 2;
                float vx = fmaxf(acc[mt][nt][half_ * 2 + 0] + sB[col], 0.f);
                float vy = fmaxf(acc[mt][nt][half_ * 2 + 1] + sB[col + 1], 0.f);
                if (outh) {
                    __half2 hp = __floats2half2_rn(vx, vy);
                    *(uint32_t*)(outh + (size_t)r * 128 + col) = h2_bits(hp);
                    float2 hr = __half22float2(hp);
                    __half2 lp = __floats2half2_rn(vx - hr.x, vy - hr.y);
                    *(uint32_t*)(outl + (size_t)r * 128 + col) = h2_bits(lp);
                }
                if (batch) {
                    float* pp = g_pool + (size_t)bi * 256 + poolOff + col;
                    atomicAdd(pp + 0, vx);
                    atomicAdd(pp + 1, vy);
                }
            }
        }
    }
}

// ---------------- head ----------------
__global__ void k_head(const float* __restrict__ gamma, const float* __restrict__ beta,
                       const float* __restrict__ rm, const float* __restrict__ rv,
                       const float* __restrict__ W1, const float* __restrict__ b1,
                       const float* __restrict__ W2, const float* __restrict__ b2,
                       float* __restrict__ out)
{
    __shared__ float sg[256];
    __shared__ float s1[128];
    __shared__ float s2[10];
    int gb = blockIdx.x, t = threadIdx.x;
    for (int i = t; i < 256; i += 128) {
        float v = g_pool[gb * 256 + i];
        v = (v - rm[i]) * rsqrtf(rv[i] + 1e-5f) * gamma[i] + beta[i];
        sg[i] = v;
    }
    __syncthreads();
    float acc = b1[t];
    #pragma unroll 8
    for (int k = 0; k < 256; k++) acc += sg[k] * W1[k * 128 + t];
    s1[t] = fmaxf(acc, 0.f);
    __syncthreads();
    if (t < 10) {
        float a = b2[t];
        #pragma unroll 8
        for (int k = 0; k < 128; k++) a += s1[k] * W2[k * 10 + t];
        s2[t] = a;
    }
    __syncthreads();
    if (t == 0) {
        float m = s2[0];
        for (int j = 1; j < 10; j++) m = fmaxf(m, s2[j]);
        float ex[10]; float sum = 0.f;
        for (int j = 0; j < 10; j++) { ex[j] = expf(s2[j] - m); sum += ex[j]; }
        float inv = 1.0f / sum;
        for (int j = 0; j < 10; j++) out[gb * 10 + j] = ex[j] * inv;
    }
}

// ---------------- host launch ----------------
extern "C" void kernel_launch(void* const* d_in, const int* in_sizes, int n_in,
                              void* d_out, int out_size)
{
    const float* x     = (const float*)d_in[0];
    const int*   ei    = (const int*)d_in[1];
    const int*   batch = (const int*)d_in[2];
    int base = (n_in > 3 && in_sizes[3] == 1) ? 4 : 3;

    const float* p[24];
    for (int i = 0; i < 24; i++) p[i] = (const float*)d_in[base + i];

    const int* src = ei;
    const int* dst = ei + EE;

    void *pxh, *pxl, *ph1h, *ph1l, *ph2h, *ph2l;
    cudaGetSymbolAddress(&pxh,  g_xh);
    cudaGetSymbolAddress(&pxl,  g_xl);
    cudaGetSymbolAddress(&ph1h, g_h1h);
    cudaGetSymbolAddress(&ph1l, g_h1l);
    cudaGetSymbolAddress(&ph2h, g_h2h);
    cudaGetSymbolAddress(&ph2l, g_h2l);

    __half* xh  = (__half*)pxh;
    __half* xl  = (__half*)pxl;
    __half* h1h = (__half*)ph1h;
    __half* h1l = (__half*)ph1l;
    __half* h2h = (__half*)ph2h;
    __half* h2l = (__half*)ph2l;

    // x planes freed after block-0 conv1 -> reuse as block-0 output (hb)
    __half* hbh = xh;
    __half* hbl = xl;

    static cudaStream_t sSide = nullptr;
    static cudaEvent_t ev[12];
    if (sSide == nullptr) {
        cudaStreamCreate(&sSide);
        for (int i = 0; i < 12; i++)
            cudaEventCreateWithFlags(&ev[i], cudaEventDisableTiming);
        cudaFuncSetAttribute(k_p1,     cudaFuncAttributeMaxDynamicSharedMemorySize, GEMM_SMEM);
        cudaFuncSetAttribute(k_p2,     cudaFuncAttributeMaxDynamicSharedMemorySize, GEMM_SMEM);
        cudaFuncSetAttribute(k_gemmJK, cudaFuncAttributeMaxDynamicSharedMemorySize, GEMM_SMEM);
    }

    const int AGG_BLOCKS = (NN + 15) / 16;   // 3125

    // ---- prep: fork conversions onto side stream, CSR chain on main ----
    cudaEventRecord(ev[0], 0);
    cudaStreamWaitEvent(sSide, ev[0], 0);
    k_convxw<<<6250 + 768, 256, 0, sSide>>>(x,
        p[0], p[1], p[3], p[4], p[6], p[6] + 16384,
        p[8], p[9], p[11], p[12], p[14], p[14] + 16384);
    cudaEventRecord(ev[1], sSide);

    k_count<<<6250, 256>>>(dst);
    k_scan<<<1, 1024>>>();
    k_fillcsr<<<6250, 256>>>(src, dst);
    cudaStreamWaitEvent(0, ev[1], 0);

    // ---- layer helper pattern: fork agg || P2, join, P1 ----
    // layer 0: block0 conv1
    cudaEventRecord(ev[2], 0);
    cudaStreamWaitEvent(sSide, ev[2], 0);
    k_agg<<<AGG_BLOCKS, 256, 0, sSide>>>(xh);
    cudaEventRecord(ev[3], sSide);
    k_p2<<<NGB, 256, GEMM_SMEM>>>(xh, xl, 1);
    cudaStreamWaitEvent(0, ev[3], 0);
    k_p1<<<NGB, 256, GEMM_SMEM>>>(0, p[2], h1h, h1l);

    // layer 1: block0 conv2
    cudaEventRecord(ev[4], 0);
    cudaStreamWaitEvent(sSide, ev[4], 0);
    k_agg<<<AGG_BLOCKS, 256, 0, sSide>>>(h1h);
    cudaEventRecord(ev[5], sSide);
    k_p2<<<NGB, 256, GEMM_SMEM>>>(h1h, h1l, 3);
    cudaStreamWaitEvent(0, ev[5], 0);
    k_p1<<<NGB, 256, GEMM_SMEM>>>(2, p[5], h2h, h2l);

    // block0 JK + pool 0 (output into freed x planes)
    k_gemmJK<<<NGB, 256, GEMM_SMEM>>>(h1h, h1l, 4, h2h, h2l, 5, p[7], hbh, hbl, batch, 0);

    // layer 2: block1 conv1
    cudaEventRecord(ev[6], 0);
    cudaStreamWaitEvent(sSide, ev[6], 0);
    k_agg<<<AGG_BLOCKS, 256, 0, sSide>>>(hbh);
    cudaEventRecord(ev[7], sSide);
    k_p2<<<NGB, 256, GEMM_SMEM>>>(hbh, hbl, 7);
    cudaStreamWaitEvent(0, ev[7], 0);
    k_p1<<<NGB, 256, GEMM_SMEM>>>(6, p[10], h1h, h1l);

    // layer 3: block1 conv2
    cudaEventRecord(ev[8], 0);
    cudaStreamWaitEvent(sSide, ev[8], 0);
    k_agg<<<AGG_BLOCKS, 256, 0, sSide>>>(h1h);
    cudaEventRecord(ev[9], sSide);
    k_p2<<<NGB, 256, GEMM_SMEM>>>(h1h, h1l, 9);
    cudaStreamWaitEvent(0, ev[9], 0);
    k_p1<<<NGB, 256, GEMM_SMEM>>>(8, p[13], h2h, h2l);

    // block1 JK + pool 1 (pool only)
    k_gemmJK<<<NGB, 256, GEMM_SMEM>>>(h1h, h1l, 10, h2h, h2l, 11, p[15],
                                      nullptr, nullptr, batch, 128);

    // ---- head ----
    k_head<<<GG, 128>>>(p[16], p[17], p[18], p[19], p[20], p[21], p[22], p[23],
                        (float*)d_out);

    // ---- tail: restore zeroed state for the next call ----
    k_zero2<<<452, 256>>>();
}

// round 15
// speedup vs baseline: 1.2586x; 1.0994x over previous
#include <cuda_runtime.h>
#include <cuda_fp16.h>
#include <cstdint>
#include <math.h>

#define NN 50000
#define EE 1600000
#define GG 256
#define HH 128
#define NGB 391   // ceil(50000/128)

// ---------------- scratch ----------------
__device__ int   g_row[NN + 1];
__device__ int   g_col[EE];
__device__ int   g_fill[NN];
__device__ float g_deginv[NN];
__device__ float g_pool[GG * 2 * HH];
// fp16 hi/lo activation planes
__device__ __align__(16) __half g_xh[NN * HH], g_xl[NN * HH];
__device__ __align__(16) __half g_mh[NN * HH], g_ml[NN * HH];
__device__ __align__(16) __half g_h1h[NN * HH], g_h1l[NN * HH];
__device__ __align__(16) __half g_h2h[NN * HH], g_h2l[NN * HH];
// 12 weight slots of 128x128, fp16 (hi only — 2-term scheme)
__device__ __align__(16) __half g_Wh[12 * 16384];

__device__ __forceinline__ uint32_t smem_u32(const void* p) {
    uint32_t a;
    asm("{ .reg .u64 t; cvta.to.shared.u64 t, %1; cvt.u32.u64 %0, t; }" : "=r"(a) : "l"(p));
    return a;
}
__device__ __forceinline__ uint32_t h2_bits(__half2 h) { return *(uint32_t*)&h; }

// ---------------- prep kernels ----------------
// runs at TAIL of each call (globals zero-initialized at load, so call 1 is fine)
__global__ void k_zero2() {
    int b = blockIdx.x;
    if (b < 196) {
        int i = b * 256 + threadIdx.x;
        if (i < NN) g_fill[i] = 0;
    } else {
        int i = (b - 196) * 256 + threadIdx.x;
        if (i < GG * 256) g_pool[i] = 0.f;
    }
}

__global__ void k_count(const int* __restrict__ dst) {
    int e = blockIdx.x * 256 + threadIdx.x;
    if (e < EE) atomicAdd(&g_fill[dst[e]], 1);
}

// x->fp16 hi/lo planes | W->fp16 (side stream, overlapped with CSR build)
__global__ void k_convxw(const float* __restrict__ x,
                         const float* s0, const float* s1, const float* s2, const float* s3,
                         const float* s4, const float* s5, const float* s6, const float* s7,
                         const float* s8, const float* s9, const float* s10, const float* s11)
{
    int b = blockIdx.x;
    if (b < 6250) {
        int i = (b * 256 + threadIdx.x) * 4;
        float4 v = *(const float4*)(x + i);
        __half2 h01 = __floats2half2_rn(v.x, v.y);
        __half2 h23 = __floats2half2_rn(v.z, v.w);
        *(uint2*)(g_xh + i) = make_uint2(h2_bits(h01), h2_bits(h23));
        float2 r01 = __half22float2(h01);
        float2 r23 = __half22float2(h23);
        __half2 l01 = __floats2half2_rn(v.x - r01.x, v.y - r01.y);
        __half2 l23 = __floats2half2_rn(v.z - r23.x, v.w - r23.y);
        *(uint2*)(g_xl + i) = make_uint2(h2_bits(l01), h2_bits(l23));
    } else {
        int idx = (b - 6250) * 256 + threadIdx.x;   // 12*16384
        int slot = idx >> 14;
        int w = idx & 16383;
        const float* src;
        switch (slot) {
            case 0: src = s0; break; case 1: src = s1; break;
            case 2: src = s2; break; case 3: src = s3; break;
            case 4: src = s4; break; case 5: src = s5; break;
            case 6: src = s6; break; case 7: src = s7; break;
            case 8: src = s8; break; case 9: src = s9; break;
            case 10: src = s10; break; default: src = s11; break;
        }
        g_Wh[idx] = __float2half_rn(src[w]);
    }
}

__global__ void k_scan() {
    __shared__ int ssum[1024];
    int t = threadIdx.x;
    const int C = (NN + 1023) / 1024;
    int s = t * C;
    int e = s + C; if (e > NN) e = NN;
    int loc = 0;
    for (int i = s; i < e; i++) loc += g_fill[i];
    ssum[t] = loc;
    __syncthreads();
    if (t == 0) {
        int run = 0;
        for (int i = 0; i < 1024; i++) { int v = ssum[i]; ssum[i] = run; run += v; }
        g_row[NN] = run;
    }
    __syncthreads();
    int run = ssum[t];
    for (int i = s; i < e; i++) {
        int c = g_fill[i];
        g_row[i]    = run;
        g_fill[i]   = run;
        g_deginv[i] = 1.0f / fmaxf((float)c, 1.0f);
        run += c;
    }
}
__global__ void k_fillcsr(const int* __restrict__ src, const int* __restrict__ dst) {
    int e = blockIdx.x * blockDim.x + threadIdx.x;
    if (e < EE) {
        int pos = atomicAdd(&g_fill[dst[e]], 1);
        g_col[pos] = src[e];
    }
}

// ---------------- aggregation: 2 nodes/warp, 16 lanes x uint4 ----------------
__global__ __launch_bounds__(256) void k_agg(const __half* __restrict__ inh) {
    int tid = threadIdx.x;
    int warp = tid >> 5, lane = tid & 31;
    int l16 = lane & 15;
    int n = blockIdx.x * 16 + warp * 2 + (lane >> 4);
    if (n >= NN) return;
    int s = g_row[n], e = g_row[n + 1];
    float a0 = 0.f, a1 = 0.f, a2 = 0.f, a3 = 0.f;
    float a4 = 0.f, a5 = 0.f, a6 = 0.f, a7 = 0.f;
    const __half* bh = inh + l16 * 8;
    #pragma unroll 4
    for (int i = s; i < e; i++) {
        int cc = __ldg(&g_col[i]);
        uint4 u = *(const uint4*)(bh + (size_t)cc * HH);
        float2 f0 = __half22float2(*(__half2*)&u.x);
        float2 f1 = __half22float2(*(__half2*)&u.y);
        float2 f2 = __half22float2(*(__half2*)&u.z);
        float2 f3 = __half22float2(*(__half2*)&u.w);
        a0 += f0.x; a1 += f0.y; a2 += f1.x; a3 += f1.y;
        a4 += f2.x; a5 += f2.y; a6 += f3.x; a7 += f3.y;
    }
    float d = g_deginv[n];
    a0 *= d; a1 *= d; a2 *= d; a3 *= d;
    a4 *= d; a5 *= d; a6 *= d; a7 *= d;
    __half2 hp0 = __floats2half2_rn(a0, a1);
    __half2 hp1 = __floats2half2_rn(a2, a3);
    __half2 hp2 = __floats2half2_rn(a4, a5);
    __half2 hp3 = __floats2half2_rn(a6, a7);
    *(uint4*)(g_mh + (size_t)n * HH + l16 * 8) =
        make_uint4(h2_bits(hp0), h2_bits(hp1), h2_bits(hp2), h2_bits(hp3));
    float2 r0 = __half22float2(hp0), r1 = __half22float2(hp1);
    float2 r2 = __half22float2(hp2), r3 = __half22float2(hp3);
    __half2 lp0 = __floats2half2_rn(a0 - r0.x, a1 - r0.y);
    __half2 lp1 = __floats2half2_rn(a2 - r1.x, a3 - r1.y);
    __half2 lp2 = __floats2half2_rn(a4 - r2.x, a5 - r2.y);
    __half2 lp3 = __floats2half2_rn(a6 - r3.x, a7 - r3.y);
    *(uint4*)(g_ml + (size_t)n * HH + l16 * 8) =
        make_uint4(h2_bits(lp0), h2_bits(lp1), h2_bits(lp2), h2_bits(lp3));
}

// ---------------- GEMM (R12 shape: 128x128 tile, 2 CTA/SM) ----------------
// SMEM: Ah 32KB | Al 32KB | Wh 16KB | bias
static constexpr int OFF_AH = 0;
static constexpr int OFF_AL = 32768;
static constexpr int OFF_WH = 65536;
static constexpr int OFF_BI = 81920;
static constexpr int GEMM_SMEM = 82432;

__device__ __forceinline__ uint32_t swz(uint32_t row, uint32_t kbyte) {
    uint32_t col16 = kbyte >> 4;
    uint32_t scol = col16 ^ (row & 7);
    return row * 256 + scol * 16 + (kbyte & 15);
}
__device__ __forceinline__ void ldsm_x4(uint32_t* r, uint32_t addr) {
    asm volatile("ldmatrix.sync.aligned.m8n8.x4.shared.b16 {%0,%1,%2,%3}, [%4];"
                 : "=r"(r[0]), "=r"(r[1]), "=r"(r[2]), "=r"(r[3]) : "r"(addr));
}
__device__ __forceinline__ void ldsm_x4_t(uint32_t* r, uint32_t addr) {
    asm volatile("ldmatrix.sync.aligned.m8n8.x4.trans.shared.b16 {%0,%1,%2,%3}, [%4];"
                 : "=r"(r[0]), "=r"(r[1]), "=r"(r[2]), "=r"(r[3]) : "r"(addr));
}
__device__ __forceinline__ void mma16816(float* c, const uint32_t* a, uint32_t b0, uint32_t b1) {
    asm volatile(
        "mma.sync.aligned.m16n8k16.row.col.f32.f16.f16.f32 "
        "{%0,%1,%2,%3}, {%4,%5,%6,%7}, {%8,%9}, {%0,%1,%2,%3};"
        : "+f"(c[0]), "+f"(c[1]), "+f"(c[2]), "+f"(c[3])
        : "r"(a[0]), "r"(a[1]), "r"(a[2]), "r"(a[3]), "r"(b0), "r"(b1));
}

// one panel, 2-term: (Ah + Al) @ Wh over K=128 from resident A planes
__device__ __forceinline__ void panel_mma(
    float acc[2][8][4], int slot, char* smem, uint32_t sb,
    int tid, int lane, int wm, int wn)
{
    const __half* wh = g_Wh + slot * 16384;
    uint32_t aRow = (uint32_t)(wm + (lane & 15));
    uint32_t aKadd = (uint32_t)((lane >> 4) * 16);
    uint32_t wRowL = (uint32_t)(lane & 15);
    uint32_t nAdd = (uint32_t)((lane >> 4) * 16);
    int k = tid >> 2, q4 = tid & 3;

    #pragma unroll
    for (int c = 0; c < 2; c++) {
        __syncthreads();   // A visible / prev W consumed
        {
            const uint4* whp = (const uint4*)(wh + (size_t)(c * 64 + k) * 128 + q4 * 32);
            #pragma unroll
            for (int q = 0; q < 4; q++) {
                uint32_t b = (uint32_t)(q4 * 64 + q * 16);
                *(uint4*)(smem + OFF_WH + swz((uint32_t)k, b)) = whp[q];
            }
        }
        __syncthreads();
        #pragma unroll
        for (int ks = 0; ks < 4; ks++) {
            uint32_t kb = (uint32_t)(c * 128 + ks * 32) + aKadd;
            uint32_t ah0[4], ah1[4], al0[4], al1[4];
            ldsm_x4(ah0, sb + OFF_AH + swz(aRow, kb));
            ldsm_x4(ah1, sb + OFF_AH + swz(aRow + 16, kb));
            ldsm_x4(al0, sb + OFF_AL + swz(aRow, kb));
            ldsm_x4(al1, sb + OFF_AL + swz(aRow + 16, kb));
            uint32_t wRow = (uint32_t)(ks * 16) + wRowL;
            #pragma unroll
            for (int bt = 0; bt < 4; bt++) {
                uint32_t nb = (uint32_t)((wn + bt * 16) * 2) + nAdd;
                uint32_t bh[4];
                ldsm_x4_t(bh, sb + OFF_WH + swz(wRow, nb));
                mma16816(acc[0][bt * 2 + 0], ah0, bh[0], bh[1]);
                mma16816(acc[0][bt * 2 + 1], ah0, bh[2], bh[3]);
                mma16816(acc[1][bt * 2 + 0], ah1, bh[0], bh[1]);
                mma16816(acc[1][bt * 2 + 1], ah1, bh[2], bh[3]);
                mma16816(acc[0][bt * 2 + 0], al0, bh[0], bh[1]);
                mma16816(acc[0][bt * 2 + 1], al0, bh[2], bh[3]);
                mma16816(acc[1][bt * 2 + 0], al1, bh[0], bh[1]);
                mma16816(acc[1][bt * 2 + 1], al1, bh[2], bh[3]);
            }
        }
    }
}

// stage direct plane rows into SMEM A (full K=128)
__device__ __forceinline__ void stage_direct(
    const __half* Ah, const __half* Al,
    int m0, int tid, char* smem)
{
    int r = tid >> 1, half_ = tid & 1;
    int gr = m0 + r; if (gr > NN - 1) gr = NN - 1;
    size_t gofs = (size_t)gr * 128 + half_ * 64;
    const uint4* aph = (const uint4*)(Ah + gofs);
    const uint4* apl = (const uint4*)(Al + gofs);
    #pragma unroll
    for (int q = 0; q < 8; q++) {
        uint32_t kb = (uint32_t)(half_ * 128 + q * 16);
        uint32_t so = swz((uint32_t)r, kb);
        *(uint4*)(smem + OFF_AH + so) = aph[q];
        *(uint4*)(smem + OFF_AL + so) = apl[q];
    }
}

// epilogue: bias+relu; plane store and/or pool
__device__ __forceinline__ void epilogue(
    float acc[2][8][4], const float* sB,
    __half* outh, __half* outl,
    const int* batch, int poolOff,
    int m0, int lane, int wm, int wn)
{
    int g = lane >> 2, tg = lane & 3;
    #pragma unroll
    for (int mt = 0; mt < 2; mt++) {
        #pragma unroll
        for (int half_ = 0; half_ < 2; half_++) {
            int r = m0 + wm + mt * 16 + g + half_ * 8;
            if (r >= NN) continue;
            int bi = batch ? batch[r] : 0;
            #pragma unroll
            for (int nt = 0; nt < 8; nt++) {
                int col = wn + nt * 8 + tg * 2;
                float vx = fmaxf(acc[mt][nt][half_ * 2 + 0] + sB[col], 0.f);
                float vy = fmaxf(acc[mt][nt][half_ * 2 + 1] + sB[col + 1], 0.f);
                if (outh) {
                    __half2 hp = __floats2half2_rn(vx, vy);
                    *(uint32_t*)(outh + (size_t)r * 128 + col) = h2_bits(hp);
                    float2 hr = __half22float2(hp);
                    __half2 lp = __floats2half2_rn(vx - hr.x, vy - hr.y);
                    *(uint32_t*)(outl + (size_t)r * 128 + col) = h2_bits(lp);
                }
                if (batch) {
                    float* pp = g_pool + (size_t)bi * 256 + poolOff + col;
                    atomicAdd(pp + 0, vx);
                    atomicAdd(pp + 1, vy);
                }
            }
        }
    }
}

// ---------------- conv GEMM: relu(mean@slotL + in@slotR + bias) -> planes ----------------
__global__ __launch_bounds__(256, 2) void k_conv(
    const __half* __restrict__ inh, const __half* __restrict__ inl,
    int slotL, int slotR, const float* __restrict__ bias,
    __half* __restrict__ outh, __half* __restrict__ outl)
{
    extern __shared__ char smem[];
    uint32_t sb = smem_u32(smem);
    int tid = threadIdx.x, lane = tid & 31, wid = tid >> 5;
    int wm = (wid & 3) * 32, wn = (wid >> 2) * 64;
    int m0 = blockIdx.x * 128;
    float* sB = (float*)(smem + OFF_BI);
    if (tid < 128) sB[tid] = bias[tid];

    float acc[2][8][4];
    #pragma unroll
    for (int a = 0; a < 2; a++)
        #pragma unroll
        for (int b = 0; b < 8; b++)
            #pragma unroll
            for (int c = 0; c < 4; c++) acc[a][b][c] = 0.f;

    stage_direct(g_mh, g_ml, m0, tid, smem);
    panel_mma(acc, slotL, smem, sb, tid, lane, wm, wn);
    __syncthreads();
    stage_direct(inh, inl, m0, tid, smem);
    panel_mma(acc, slotR, smem, sb, tid, lane, wm, wn);

    epilogue(acc, sB, outh, outl, nullptr, 0, m0, lane, wm, wn);
}

// JK: relu(A1@s1 + A2@s2 + bias), plane store + pool
__global__ __launch_bounds__(256, 2) void k_gemmJK(
    const __half* __restrict__ A1h, const __half* __restrict__ A1l, int s1,
    const __half* __restrict__ A2h, const __half* __restrict__ A2l, int s2,
    const float* __restrict__ bias,
    __half* __restrict__ outh, __half* __restrict__ outl,
    const int* __restrict__ batch, int poolOff)
{
    extern __shared__ char smem[];
    uint32_t sb = smem_u32(smem);
    int tid = threadIdx.x, lane = tid & 31, wid = tid >> 5;
    int wm = (wid & 3) * 32, wn = (wid >> 2) * 64;
    int m0 = blockIdx.x * 128;
    float* sB = (float*)(smem + OFF_BI);
    if (tid < 128) sB[tid] = bias[tid];

    float acc[2][8][4];
    #pragma unroll
    for (int a = 0; a < 2; a++)
        #pragma unroll
        for (int b = 0; b < 8; b++)
            #pragma unroll
            for (int c = 0; c < 4; c++) acc[a][b][c] = 0.f;

    stage_direct(A1h, A1l, m0, tid, smem);
    panel_mma(acc, s1, smem, sb, tid, lane, wm, wn);
    __syncthreads();
    stage_direct(A2h, A2l, m0, tid, smem);
    panel_mma(acc, s2, smem, sb, tid, lane, wm, wn);

    epilogue(acc, sB, outh, outl, batch, poolOff, m0, lane, wm, wn);
}

// ---------------- head ----------------
__global__ void k_head(const float* __restrict__ gamma, const float* __restrict__ beta,
                       const float* __restrict__ rm, const float* __restrict__ rv,
                       const float* __restrict__ W1, const float* __restrict__ b1,
                       const float* __restrict__ W2, const float* __restrict__ b2,
                       float* __restrict__ out)
{
    __shared__ float sg[256];
    __shared__ float s1[128];
    __shared__ float s2[10];
    int gb = blockIdx.x, t = threadIdx.x;
    for (int i = t; i < 256; i += 128) {
        float v = g_pool[gb * 256 + i];
        v = (v - rm[i]) * rsqrtf(rv[i] + 1e-5f) * gamma[i] + beta[i];
        sg[i] = v;
    }
    __syncthreads();
    float acc = b1[t];
    #pragma unroll 8
    for (int k = 0; k < 256; k++) acc += sg[k] * W1[k * 128 + t];
    s1[t] = fmaxf(acc, 0.f);
    __syncthreads();
    if (t < 10) {
        float a = b2[t];
        #pragma unroll 8
        for (int k = 0; k < 128; k++) a += s1[k] * W2[k * 10 + t];
        s2[t] = a;
    }
    __syncthreads();
    if (t == 0) {
        float m = s2[0];
        for (int j = 1; j < 10; j++) m = fmaxf(m, s2[j]);
        float ex[10]; float sum = 0.f;
        for (int j = 0; j < 10; j++) { ex[j] = expf(s2[j] - m); sum += ex[j]; }
        float inv = 1.0f / sum;
        for (int j = 0; j < 10; j++) out[gb * 10 + j] = ex[j] * inv;
    }
}

// ---------------- host launch ----------------
extern "C" void kernel_launch(void* const* d_in, const int* in_sizes, int n_in,
                              void* d_out, int out_size)
{
    const float* x     = (const float*)d_in[0];
    const int*   ei    = (const int*)d_in[1];
    const int*   batch = (const int*)d_in[2];
    int base = (n_in > 3 && in_sizes[3] == 1) ? 4 : 3;

    const float* p[24];
    for (int i = 0; i < 24; i++) p[i] = (const float*)d_in[base + i];

    const int* src = ei;
    const int* dst = ei + EE;

    void *pxh, *pxl, *ph1h, *ph1l, *ph2h, *ph2l;
    cudaGetSymbolAddress(&pxh,  g_xh);
    cudaGetSymbolAddress(&pxl,  g_xl);
    cudaGetSymbolAddress(&ph1h, g_h1h);
    cudaGetSymbolAddress(&ph1l, g_h1l);
    cudaGetSymbolAddress(&ph2h, g_h2h);
    cudaGetSymbolAddress(&ph2l, g_h2l);

    __half* xh  = (__half*)pxh;
    __half* xl  = (__half*)pxl;
    __half* h1h = (__half*)ph1h;
    __half* h1l = (__half*)ph1l;
    __half* h2h = (__half*)ph2h;
    __half* h2l = (__half*)ph2l;

    // x planes freed after block-0 conv1 -> reuse as block-0 output (hb)
    __half* hbh = xh;
    __half* hbl = xl;

    static cudaStream_t sSide = nullptr;
    static cudaEvent_t ev0, ev1;
    if (sSide == nullptr) {
        cudaStreamCreate(&sSide);
        cudaEventCreateWithFlags(&ev0, cudaEventDisableTiming);
        cudaEventCreateWithFlags(&ev1, cudaEventDisableTiming);
        cudaFuncSetAttribute(k_conv,   cudaFuncAttributeMaxDynamicSharedMemorySize, GEMM_SMEM);
        cudaFuncSetAttribute(k_gemmJK, cudaFuncAttributeMaxDynamicSharedMemorySize, GEMM_SMEM);
    }

    // ---- prep: fork conversions onto side stream, CSR chain on main ----
    cudaEventRecord(ev0, 0);
    cudaStreamWaitEvent(sSide, ev0, 0);
    k_convxw<<<6250 + 768, 256, 0, sSide>>>(x,
        p[0], p[1], p[3], p[4], p[6], p[6] + 16384,
        p[8], p[9], p[11], p[12], p[14], p[14] + 16384);
    cudaEventRecord(ev1, sSide);

    k_count<<<6250, 256>>>(dst);
    k_scan<<<1, 1024>>>();
    k_fillcsr<<<6250, 256>>>(src, dst);
    cudaStreamWaitEvent(0, ev1, 0);

    const int AGG_BLOCKS = (NN + 15) / 16;   // 3125

    // ---- block 0, conv1 ----
    k_agg<<<AGG_BLOCKS, 256>>>(xh);
    k_conv<<<NGB, 256, GEMM_SMEM>>>(xh, xl, 0, 1, p[2], h1h, h1l);
    // ---- block 0, conv2 ----
    k_agg<<<AGG_BLOCKS, 256>>>(h1h);
    k_conv<<<NGB, 256, GEMM_SMEM>>>(h1h, h1l, 2, 3, p[5], h2h, h2l);
    // ---- block 0 JK + pool 0 (output into freed x planes) ----
    k_gemmJK<<<NGB, 256, GEMM_SMEM>>>(h1h, h1l, 4, h2h, h2l, 5, p[7], hbh, hbl, batch, 0);

    // ---- block 1, conv1 ----
    k_agg<<<AGG_BLOCKS, 256>>>(hbh);
    k_conv<<<NGB, 256, GEMM_SMEM>>>(hbh, hbl, 6, 7, p[10], h1h, h1l);
    // ---- block 1, conv2 ----
    k_agg<<<AGG_BLOCKS, 256>>>(h1h);
    k_conv<<<NGB, 256, GEMM_SMEM>>>(h1h, h1l, 8, 9, p[13], h2h, h2l);
    // ---- block 1 JK + pool 1 (pool only) ----
    k_gemmJK<<<NGB, 256, GEMM_SMEM>>>(h1h, h1l, 10, h2h, h2l, 11, p[15],
                                      nullptr, nullptr, batch, 128);

    // ---- head ----
    k_head<<<GG, 128>>>(p[16], p[17], p[18], p[19], p[20], p[21], p[22], p[23],
                        (float*)d_out);

    // ---- tail: restore zeroed state for the next call ----
    k_zero2<<<452, 256>>>();
}

// round 16
// speedup vs baseline: 1.3028x; 1.0351x over previous
#include <cuda_runtime.h>
#include <cuda_fp16.h>
#include <cstdint>
#include <math.h>

#define NN 50000
#define EE 1600000
#define GG 256
#define HH 128
#define NGB 391   // ceil(50000/128)

// ---------------- scratch ----------------
__device__ int   g_row[NN + 1];
__device__ int   g_col[EE];
__device__ int   g_fill[NN];
__device__ float g_deginv[NN];
__device__ float g_pool[GG * 2 * HH];
// fp16 hi/lo activation planes
__device__ __align__(16) __half g_xh[NN * HH], g_xl[NN * HH];
__device__ __align__(16) __half g_mh[NN * HH], g_ml[NN * HH];
__device__ __align__(16) __half g_h1h[NN * HH], g_h1l[NN * HH];
// 12 weight slots of 128x128, fp16 (hi only — 2-term scheme)
__device__ __align__(16) __half g_Wh[12 * 16384];

__device__ __forceinline__ uint32_t smem_u32(const void* p) {
    uint32_t a;
    asm("{ .reg .u64 t; cvta.to.shared.u64 t, %1; cvt.u32.u64 %0, t; }" : "=r"(a) : "l"(p));
    return a;
}
__device__ __forceinline__ uint32_t h2_bits(__half2 h) { return *(uint32_t*)&h; }

// ---------------- prep kernels ----------------
// runs at TAIL of each call (globals zero-initialized at load, so call 1 is fine)
__global__ void k_zero2() {
    int b = blockIdx.x;
    if (b < 196) {
        int i = b * 256 + threadIdx.x;
        if (i < NN) g_fill[i] = 0;
    } else {
        int i = (b - 196) * 256 + threadIdx.x;
        if (i < GG * 256) g_pool[i] = 0.f;
    }
}

__global__ void k_count(const int* __restrict__ dst) {
    int e = blockIdx.x * 256 + threadIdx.x;
    if (e < EE) atomicAdd(&g_fill[dst[e]], 1);
}

// x->fp16 hi/lo planes | W->fp16 (side stream, overlapped with CSR build)
__global__ void k_convxw(const float* __restrict__ x,
                         const float* s0, const float* s1, const float* s2, const float* s3,
                         const float* s4, const float* s5, const float* s6, const float* s7,
                         const float* s8, const float* s9, const float* s10, const float* s11)
{
    int b = blockIdx.x;
    if (b < 6250) {
        int i = (b * 256 + threadIdx.x) * 4;
        float4 v = *(const float4*)(x + i);
        __half2 h01 = __floats2half2_rn(v.x, v.y);
        __half2 h23 = __floats2half2_rn(v.z, v.w);
        *(uint2*)(g_xh + i) = make_uint2(h2_bits(h01), h2_bits(h23));
        float2 r01 = __half22float2(h01);
        float2 r23 = __half22float2(h23);
        __half2 l01 = __floats2half2_rn(v.x - r01.x, v.y - r01.y);
        __half2 l23 = __floats2half2_rn(v.z - r23.x, v.w - r23.y);
        *(uint2*)(g_xl + i) = make_uint2(h2_bits(l01), h2_bits(l23));
    } else {
        int idx = (b - 6250) * 256 + threadIdx.x;   // 12*16384
        int slot = idx >> 14;
        int w = idx & 16383;
        const float* src;
        switch (slot) {
            case 0: src = s0; break; case 1: src = s1; break;
            case 2: src = s2; break; case 3: src = s3; break;
            case 4: src = s4; break; case 5: src = s5; break;
            case 6: src = s6; break; case 7: src = s7; break;
            case 8: src = s8; break; case 9: src = s9; break;
            case 10: src = s10; break; default: src = s11; break;
        }
        g_Wh[idx] = __float2half_rn(src[w]);
    }
}

__global__ void k_scan() {
    __shared__ int ssum[1024];
    int t = threadIdx.x;
    const int C = (NN + 1023) / 1024;
    int s = t * C;
    int e = s + C; if (e > NN) e = NN;
    int loc = 0;
    for (int i = s; i < e; i++) loc += g_fill[i];
    ssum[t] = loc;
    __syncthreads();
    if (t == 0) {
        int run = 0;
        for (int i = 0; i < 1024; i++) { int v = ssum[i]; ssum[i] = run; run += v; }
        g_row[NN] = run;
    }
    __syncthreads();
    int run = ssum[t];
    for (int i = s; i < e; i++) {
        int c = g_fill[i];
        g_row[i]    = run;
        g_fill[i]   = run;
        g_deginv[i] = 1.0f / fmaxf((float)c, 1.0f);
        run += c;
    }
}
__global__ void k_fillcsr(const int* __restrict__ src, const int* __restrict__ dst) {
    int e = blockIdx.x * blockDim.x + threadIdx.x;
    if (e < EE) {
        int pos = atomicAdd(&g_fill[dst[e]], 1);
        g_col[pos] = src[e];
    }
}

// ---------------- aggregation: 2 nodes/warp, 16 lanes x uint4 ----------------
__global__ __launch_bounds__(256) void k_agg(const __half* __restrict__ inh) {
    int tid = threadIdx.x;
    int warp = tid >> 5, lane = tid & 31;
    int l16 = lane & 15;
    int n = blockIdx.x * 16 + warp * 2 + (lane >> 4);
    if (n >= NN) return;
    int s = g_row[n], e = g_row[n + 1];
    float a0 = 0.f, a1 = 0.f, a2 = 0.f, a3 = 0.f;
    float a4 = 0.f, a5 = 0.f, a6 = 0.f, a7 = 0.f;
    const __half* bh = inh + l16 * 8;
    #pragma unroll 4
    for (int i = s; i < e; i++) {
        int cc = __ldg(&g_col[i]);
        uint4 u = *(const uint4*)(bh + (size_t)cc * HH);
        float2 f0 = __half22float2(*(__half2*)&u.x);
        float2 f1 = __half22float2(*(__half2*)&u.y);
        float2 f2 = __half22float2(*(__half2*)&u.z);
        float2 f3 = __half22float2(*(__half2*)&u.w);
        a0 += f0.x; a1 += f0.y; a2 += f1.x; a3 += f1.y;
        a4 += f2.x; a5 += f2.y; a6 += f3.x; a7 += f3.y;
    }
    float d = g_deginv[n];
    a0 *= d; a1 *= d; a2 *= d; a3 *= d;
    a4 *= d; a5 *= d; a6 *= d; a7 *= d;
    __half2 hp0 = __floats2half2_rn(a0, a1);
    __half2 hp1 = __floats2half2_rn(a2, a3);
    __half2 hp2 = __floats2half2_rn(a4, a5);
    __half2 hp3 = __floats2half2_rn(a6, a7);
    *(uint4*)(g_mh + (size_t)n * HH + l16 * 8) =
        make_uint4(h2_bits(hp0), h2_bits(hp1), h2_bits(hp2), h2_bits(hp3));
    float2 r0 = __half22float2(hp0), r1 = __half22float2(hp1);
    float2 r2 = __half22float2(hp2), r3 = __half22float2(hp3);
    __half2 lp0 = __floats2half2_rn(a0 - r0.x, a1 - r0.y);
    __half2 lp1 = __floats2half2_rn(a2 - r1.x, a3 - r1.y);
    __half2 lp2 = __floats2half2_rn(a4 - r2.x, a5 - r2.y);
    __half2 lp3 = __floats2half2_rn(a6 - r3.x, a7 - r3.y);
    *(uint4*)(g_ml + (size_t)n * HH + l16 * 8) =
        make_uint4(h2_bits(lp0), h2_bits(lp1), h2_bits(lp2), h2_bits(lp3));
}

// ---------------- GEMM (128x128 tile, 2 CTA/SM) ----------------
// SMEM: Ah 32KB | Al 32KB | Wh 16KB | bias
static constexpr int OFF_AH = 0;
static constexpr int OFF_AL = 32768;
static constexpr int OFF_WH = 65536;
static constexpr int OFF_BI = 81920;
static constexpr int GEMM_SMEM = 82432;

__device__ __forceinline__ uint32_t swz(uint32_t row, uint32_t kbyte) {
    uint32_t col16 = kbyte >> 4;
    uint32_t scol = col16 ^ (row & 7);
    return row * 256 + scol * 16 + (kbyte & 15);
}
__device__ __forceinline__ void ldsm_x4(uint32_t* r, uint32_t addr) {
    asm volatile("ldmatrix.sync.aligned.m8n8.x4.shared.b16 {%0,%1,%2,%3}, [%4];"
                 : "=r"(r[0]), "=r"(r[1]), "=r"(r[2]), "=r"(r[3]) : "r"(addr));
}
__device__ __forceinline__ void ldsm_x4_t(uint32_t* r, uint32_t addr) {
    asm volatile("ldmatrix.sync.aligned.m8n8.x4.trans.shared.b16 {%0,%1,%2,%3}, [%4];"
                 : "=r"(r[0]), "=r"(r[1]), "=r"(r[2]), "=r"(r[3]) : "r"(addr));
}
__device__ __forceinline__ void mma16816(float* c, const uint32_t* a, uint32_t b0, uint32_t b1) {
    asm volatile(
        "mma.sync.aligned.m16n8k16.row.col.f32.f16.f16.f32 "
        "{%0,%1,%2,%3}, {%4,%5,%6,%7}, {%8,%9}, {%0,%1,%2,%3};"
        : "+f"(c[0]), "+f"(c[1]), "+f"(c[2]), "+f"(c[3])
        : "r"(a[0]), "r"(a[1]), "r"(a[2]), "r"(a[3]), "r"(b0), "r"(b1));
}

// one panel, 2-term: (Ah + Al) @ Wh over K=128 from resident A planes
__device__ __forceinline__ void panel_mma(
    float acc[2][8][4], int slot, char* smem, uint32_t sb,
    int tid, int lane, int wm, int wn)
{
    const __half* wh = g_Wh + slot * 16384;
    uint32_t aRow = (uint32_t)(wm + (lane & 15));
    uint32_t aKadd = (uint32_t)((lane >> 4) * 16);
    uint32_t wRowL = (uint32_t)(lane & 15);
    uint32_t nAdd = (uint32_t)((lane >> 4) * 16);
    int k = tid >> 2, q4 = tid & 3;

    #pragma unroll
    for (int c = 0; c < 2; c++) {
        __syncthreads();   // A visible / prev W consumed
        {
            const uint4* whp = (const uint4*)(wh + (size_t)(c * 64 + k) * 128 + q4 * 32);
            #pragma unroll
            for (int q = 0; q < 4; q++) {
                uint32_t b = (uint32_t)(q4 * 64 + q * 16);
                *(uint4*)(smem + OFF_WH + swz((uint32_t)k, b)) = whp[q];
            }
        }
        __syncthreads();
        #pragma unroll
        for (int ks = 0; ks < 4; ks++) {
            uint32_t kb = (uint32_t)(c * 128 + ks * 32) + aKadd;
            uint32_t ah0[4], ah1[4], al0[4], al1[4];
            ldsm_x4(ah0, sb + OFF_AH + swz(aRow, kb));
            ldsm_x4(ah1, sb + OFF_AH + swz(aRow + 16, kb));
            ldsm_x4(al0, sb + OFF_AL + swz(aRow, kb));
            ldsm_x4(al1, sb + OFF_AL + swz(aRow + 16, kb));
            uint32_t wRow = (uint32_t)(ks * 16) + wRowL;
            #pragma unroll
            for (int bt = 0; bt < 4; bt++) {
                uint32_t nb = (uint32_t)((wn + bt * 16) * 2) + nAdd;
                uint32_t bh[4];
                ldsm_x4_t(bh, sb + OFF_WH + swz(wRow, nb));
                mma16816(acc[0][bt * 2 + 0], ah0, bh[0], bh[1]);
                mma16816(acc[0][bt * 2 + 1], ah0, bh[2], bh[3]);
                mma16816(acc[1][bt * 2 + 0], ah1, bh[0], bh[1]);
                mma16816(acc[1][bt * 2 + 1], ah1, bh[2], bh[3]);
                mma16816(acc[0][bt * 2 + 0], al0, bh[0], bh[1]);
                mma16816(acc[0][bt * 2 + 1], al0, bh[2], bh[3]);
                mma16816(acc[1][bt * 2 + 0], al1, bh[0], bh[1]);
                mma16816(acc[1][bt * 2 + 1], al1, bh[2], bh[3]);
            }
        }
    }
}

// stage direct plane rows into SMEM A (full K=128)
__device__ __forceinline__ void stage_direct(
    const __half* Ah, const __half* Al,
    int m0, int tid, char* smem)
{
    int r = tid >> 1, half_ = tid & 1;
    int gr = m0 + r; if (gr > NN - 1) gr = NN - 1;
    size_t gofs = (size_t)gr * 128 + half_ * 64;
    const uint4* aph = (const uint4*)(Ah + gofs);
    const uint4* apl = (const uint4*)(Al + gofs);
    #pragma unroll
    for (int q = 0; q < 8; q++) {
        uint32_t kb = (uint32_t)(half_ * 128 + q * 16);
        uint32_t so = swz((uint32_t)r, kb);
        *(uint4*)(smem + OFF_AH + so) = aph[q];
        *(uint4*)(smem + OFF_AL + so) = apl[q];
    }
}

// epilogue: bias+relu; plane store and/or pool
__device__ __forceinline__ void epilogue(
    float acc[2][8][4], const float* sB,
    __half* outh, __half* outl,
    const int* batch, int poolOff,
    int m0, int lane, int wm, int wn)
{
    int g = lane >> 2, tg = lane & 3;
    #pragma unroll
    for (int mt = 0; mt < 2; mt++) {
        #pragma unroll
        for (int half_ = 0; half_ < 2; half_++) {
            int r = m0 + wm + mt * 16 + g + half_ * 8;
            if (r >= NN) continue;
            int bi = batch ? batch[r] : 0;
            #pragma unroll
            for (int nt = 0; nt < 8; nt++) {
                int col = wn + nt * 8 + tg * 2;
                float vx = fmaxf(acc[mt][nt][half_ * 2 + 0] + sB[col], 0.f);
                float vy = fmaxf(acc[mt][nt][half_ * 2 + 1] + sB[col + 1], 0.f);
                if (outh) {
                    __half2 hp = __floats2half2_rn(vx, vy);
                    *(uint32_t*)(outh + (size_t)r * 128 + col) = h2_bits(hp);
                    float2 hr = __half22float2(hp);
                    __half2 lp = __floats2half2_rn(vx - hr.x, vy - hr.y);
                    *(uint32_t*)(outl + (size_t)r * 128 + col) = h2_bits(lp);
                }
                if (batch) {
                    float* pp = g_pool + (size_t)bi * 256 + poolOff + col;
                    atomicAdd(pp + 0, vx);
                    atomicAdd(pp + 1, vy);
                }
            }
        }
    }
}

// ---------------- conv1 GEMM: relu(mean@slotL + in@slotR + bias) -> planes ----------------
__global__ __launch_bounds__(256, 2) void k_conv(
    const __half* __restrict__ inh, const __half* __restrict__ inl,
    int slotL, int slotR, const float* __restrict__ bias,
    __half* __restrict__ outh, __half* __restrict__ outl)
{
    extern __shared__ char smem[];
    uint32_t sb = smem_u32(smem);
    int tid = threadIdx.x, lane = tid & 31, wid = tid >> 5;
    int wm = (wid & 3) * 32, wn = (wid >> 2) * 64;
    int m0 = blockIdx.x * 128;
    float* sB = (float*)(smem + OFF_BI);
    if (tid < 128) sB[tid] = bias[tid];

    float acc[2][8][4];
    #pragma unroll
    for (int a = 0; a < 2; a++)
        #pragma unroll
        for (int b = 0; b < 8; b++)
            #pragma unroll
            for (int c = 0; c < 4; c++) acc[a][b][c] = 0.f;

    stage_direct(g_mh, g_ml, m0, tid, smem);
    panel_mma(acc, slotL, smem, sb, tid, lane, wm, wn);
    __syncthreads();
    stage_direct(inh, inl, m0, tid, smem);
    panel_mma(acc, slotR, smem, sb, tid, lane, wm, wn);

    epilogue(acc, sB, outh, outl, nullptr, 0, m0, lane, wm, wn);
}

// ---------------- fused conv2+JK ----------------
// h2 = relu(mean@sL2 + h1@sR2 + b2)   [kept in SMEM planes, never hits global]
// out = relu(h1@sJK1 + h2@sJK2 + bJK) -> optional planes + fused pool
__global__ __launch_bounds__(256, 2) void k_conv2jk(
    const __half* __restrict__ h1h, const __half* __restrict__ h1l,
    int sL2, int sR2, const float* __restrict__ b2,
    int sJK1, int sJK2, const float* __restrict__ bJK,
    __half* __restrict__ outh, __half* __restrict__ outl,
    const int* __restrict__ batch, int poolOff)
{
    extern __shared__ char smem[];
    uint32_t sb = smem_u32(smem);
    int tid = threadIdx.x, lane = tid & 31, wid = tid >> 5;
    int wm = (wid & 3) * 32, wn = (wid >> 2) * 64;
    int m0 = blockIdx.x * 128;
    float* sB = (float*)(smem + OFF_BI);
    if (tid < 128) sB[tid] = b2[tid];

    float acc[2][8][4];
    #pragma unroll
    for (int a = 0; a < 2; a++)
        #pragma unroll
        for (int b = 0; b < 8; b++)
            #pragma unroll
            for (int c = 0; c < 4; c++) acc[a][b][c] = 0.f;

    // ---- conv2: mean@Wl2 + h1@Wr2 ----
    stage_direct(g_mh, g_ml, m0, tid, smem);
    panel_mma(acc, sL2, smem, sb, tid, lane, wm, wn);
    __syncthreads();
    stage_direct(h1h, h1l, m0, tid, smem);
    panel_mma(acc, sR2, smem, sb, tid, lane, wm, wn);

    // ---- h2 = relu(acc + b2); write hi/lo planes INTO A smem; reload bias ----
    __syncthreads();   // all panel reads of A done before overwrite
    {
        int g = lane >> 2, tg = lane & 3;
        #pragma unroll
        for (int mt = 0; mt < 2; mt++) {
            #pragma unroll
            for (int half_ = 0; half_ < 2; half_++) {
                int rl = wm + mt * 16 + g + half_ * 8;   // local row 0..127
                #pragma unroll
                for (int nt = 0; nt < 8; nt++) {
                    int col = wn + nt * 8 + tg * 2;
                    float vx = fmaxf(acc[mt][nt][half_ * 2 + 0] + sB[col], 0.f);
                    float vy = fmaxf(acc[mt][nt][half_ * 2 + 1] + sB[col + 1], 0.f);
                    __half2 hp = __floats2half2_rn(vx, vy);
                    uint32_t so = swz((uint32_t)rl, (uint32_t)(col * 2));
                    *(uint32_t*)(smem + OFF_AH + so) = h2_bits(hp);
                    float2 hr = __half22float2(hp);
                    __half2 lp = __floats2half2_rn(vx - hr.x, vy - hr.y);
                    *(uint32_t*)(smem + OFF_AL + so) = h2_bits(lp);
                }
            }
        }
    }
    __syncthreads();
    if (tid < 128) sB[tid] = bJK[tid];   // swap bias to JK

    // ---- JK: h2@WlinB (A = h2 already in smem) + h1@WlinT ----
    #pragma unroll
    for (int a = 0; a < 2; a++)
        #pragma unroll
        for (int b = 0; b < 8; b++)
            #pragma unroll
            for (int c = 0; c < 4; c++) acc[a][b][c] = 0.f;

    panel_mma(acc, sJK2, smem, sb, tid, lane, wm, wn);   // h2 @ WlinB
    __syncthreads();
    stage_direct(h1h, h1l, m0, tid, smem);               // restage h1
    panel_mma(acc, sJK1, smem, sb, tid, lane, wm, wn);   // h1 @ WlinT

    epilogue(acc, sB, outh, outl, batch, poolOff, m0, lane, wm, wn);
}

// ---------------- head ----------------
__global__ void k_head(const float* __restrict__ gamma, const float* __restrict__ beta,
                       const float* __restrict__ rm, const float* __restrict__ rv,
                       const float* __restrict__ W1, const float* __restrict__ b1,
                       const float* __restrict__ W2, const float* __restrict__ b2,
                       float* __restrict__ out)
{
    __shared__ float sg[256];
    __shared__ float s1[128];
    __shared__ float s2[10];
    int gb = blockIdx.x, t = threadIdx.x;
    for (int i = t; i < 256; i += 128) {
        float v = g_pool[gb * 256 + i];
        v = (v - rm[i]) * rsqrtf(rv[i] + 1e-5f) * gamma[i] + beta[i];
        sg[i] = v;
    }
    __syncthreads();
    float acc = b1[t];
    #pragma unroll 8
    for (int k = 0; k < 256; k++) acc += sg[k] * W1[k * 128 + t];
    s1[t] = fmaxf(acc, 0.f);
    __syncthreads();
    if (t < 10) {
        float a = b2[t];
        #pragma unroll 8
        for (int k = 0; k < 128; k++) a += s1[k] * W2[k * 10 + t];
        s2[t] = a;
    }
    __syncthreads();
    if (t == 0) {
        float m = s2[0];
        for (int j = 1; j < 10; j++) m = fmaxf(m, s2[j]);
        float ex[10]; float sum = 0.f;
        for (int j = 0; j < 10; j++) { ex[j] = expf(s2[j] - m); sum += ex[j]; }
        float inv = 1.0f / sum;
        for (int j = 0; j < 10; j++) out[gb * 10 + j] = ex[j] * inv;
    }
}

// ---------------- host launch ----------------
extern "C" void kernel_launch(void* const* d_in, const int* in_sizes, int n_in,
                              void* d_out, int out_size)
{
    const float* x     = (const float*)d_in[0];
    const int*   ei    = (const int*)d_in[1];
    const int*   batch = (const int*)d_in[2];
    int base = (n_in > 3 && in_sizes[3] == 1) ? 4 : 3;

    const float* p[24];
    for (int i = 0; i < 24; i++) p[i] = (const float*)d_in[base + i];
    // b0: 0..7 (Wl1,Wr1,b1,Wl2,Wr2,b2,Wlin,blin); b1: 8..15; bn 16..19; lin1 20,21; lin2 22,23

    const int* src = ei;
    const int* dst = ei + EE;

    void *pxh, *pxl, *ph1h, *ph1l;
    cudaGetSymbolAddress(&pxh,  g_xh);
    cudaGetSymbolAddress(&pxl,  g_xl);
    cudaGetSymbolAddress(&ph1h, g_h1h);
    cudaGetSymbolAddress(&ph1l, g_h1l);

    __half* xh  = (__half*)pxh;
    __half* xl  = (__half*)pxl;
    __half* h1h = (__half*)ph1h;
    __half* h1l = (__half*)ph1l;

    // x planes freed after block-0 conv1 -> reuse as block-0 output (hb)
    __half* hbh = xh;
    __half* hbl = xl;

    static cudaStream_t sSide = nullptr;
    static cudaEvent_t ev0, ev1;
    if (sSide == nullptr) {
        cudaStreamCreate(&sSide);
        cudaEventCreateWithFlags(&ev0, cudaEventDisableTiming);
        cudaEventCreateWithFlags(&ev1, cudaEventDisableTiming);
        cudaFuncSetAttribute(k_conv,    cudaFuncAttributeMaxDynamicSharedMemorySize, GEMM_SMEM);
        cudaFuncSetAttribute(k_conv2jk, cudaFuncAttributeMaxDynamicSharedMemorySize, GEMM_SMEM);
    }

    // ---- prep: fork conversions onto side stream, CSR chain on main ----
    cudaEventRecord(ev0, 0);
    cudaStreamWaitEvent(sSide, ev0, 0);
    k_convxw<<<6250 + 768, 256, 0, sSide>>>(x,
        p[0], p[1], p[3], p[4], p[6], p[6] + 16384,
        p[8], p[9], p[11], p[12], p[14], p[14] + 16384);
    cudaEventRecord(ev1, sSide);

    k_count<<<6250, 256>>>(dst);
    k_scan<<<1, 1024>>>();
    k_fillcsr<<<6250, 256>>>(src, dst);
    cudaStreamWaitEvent(0, ev1, 0);

    const int AGG_BLOCKS = (NN + 15) / 16;   // 3125

    // ---- block 0 ----
    k_agg<<<AGG_BLOCKS, 256>>>(xh);
    k_conv<<<NGB, 256, GEMM_SMEM>>>(xh, xl, 0, 1, p[2], h1h, h1l);
    k_agg<<<AGG_BLOCKS, 256>>>(h1h);
    // conv2 + JK + pool0 fused (h2 never hits global); block output -> freed x planes
    k_conv2jk<<<NGB, 256, GEMM_SMEM>>>(h1h, h1l, 2, 3, p[5], 4, 5, p[7],
                                       hbh, hbl, batch, 0);

    // ---- block 1 ----
    k_agg<<<AGG_BLOCKS, 256>>>(hbh);
    k_conv<<<NGB, 256, GEMM_SMEM>>>(hbh, hbl, 6, 7, p[10], h1h, h1l);
    k_agg<<<AGG_BLOCKS, 256>>>(h1h);
    // conv2 + JK + pool1 fused; no output planes needed
    k_conv2jk<<<NGB, 256, GEMM_SMEM>>>(h1h, h1l, 8, 9, p[13], 10, 11, p[15],
                                       nullptr, nullptr, batch, 128);

    // ---- head ----
    k_head<<<GG, 128>>>(p[16], p[17], p[18], p[19], p[20], p[21], p[22], p[23],
                        (float*)d_out);

    // ---- tail: restore zeroed state for the next call ----
    k_zero2<<<452, 256>>>();
}